// round 5
// baseline (speedup 1.0000x reference)
#include <cuda_runtime.h>
#include <cstdint>

#define NV   64
#define NP   2016          // pairs per batch
#define NQ   504           // quads per batch
#define HQ   252           // quads per half-batch stage
#define F4B  1512          // float4 per batch (NP*3/4)
#define F4S  756           // float4 per stage
#define TPB  256
#define CHUNK 4            // batches per CTA
#define NST  (CHUNK * 2)   // stages per CTA

__device__ __forceinline__ void cp16(uint32_t dst, const float4* src) {
    asm volatile("cp.async.cg.shared.global [%0], [%1], 16;" :: "r"(dst), "l"(src));
}
__device__ __forceinline__ void cp_commit() {
    asm volatile("cp.async.commit_group;");
}

__global__ __launch_bounds__(TPB, 5) void score_kernel(
    const float* __restrict__ views,     // [B, 64, 7]
    const float* __restrict__ pairs,     // [B, 2016, 3]
    const float* __restrict__ s_a1,
    const float* __restrict__ s_a2,
    const float* __restrict__ s_gsd,
    const float* __restrict__ s_scale,
    const float* __restrict__ s_nrm,
    const float* __restrict__ s_dist,
    float* __restrict__ out,             // [B]
    int B)
{
    __shared__ float4 sbuf[2][F4S];               // 24192 B, double buffer
    __shared__ float  w[CHUNK][NV];
    __shared__ float  warpsum[CHUNK][TPB / 32];

    const int tid = threadIdx.x;
    const int b0  = blockIdx.x * CHUNK;
    const float4* pr_base = (const float4*)pairs;

    const uint32_t sb0 = (uint32_t)__cvta_generic_to_shared(&sbuf[0][0]);
    const uint32_t sb1 = (uint32_t)__cvta_generic_to_shared(&sbuf[1][0]);

    // ---- issue one stage's async copies (3 x 16B per thread, guarded) ----
    #define ISSUE_STAGE(s)                                                     \
    {                                                                          \
        int bc = b0 + ((s) >> 1);                                              \
        if (bc >= B) bc = B - 1;                                               \
        const float4* src = pr_base + (size_t)bc * F4B + ((s) & 1) * F4S;      \
        uint32_t dst = (((s) & 1) ? sb1 : sb0);                                \
        cp16(dst + tid * 16u,           src + tid);                            \
        cp16(dst + (tid + 256) * 16u,   src + tid + 256);                      \
        if (tid < F4S - 512)                                                   \
            cp16(dst + (tid + 512) * 16u, src + tid + 512);                    \
        cp_commit();                                                           \
    }

    // Kick off stage 0 immediately
    ISSUE_STAGE(0);

    // ---- scalar params (overlap in-flight copies) ----
    const float L2E = 1.4426950408889634f;
    const float a1 = *s_a1;
    const float a2 = *s_a2;
    const float c_a1 = -0.5f * L2E / (a1 * a1);
    const float c_a2 = -0.5f * L2E / (a2 * a2);
    const float sc = *s_scale;
    const float c_sc = -0.5f * L2E / (sc * sc);
    const float TH = 20.0f / 90.0f;

    // ---- all per-view weights in ONE pass: 256 threads = 4 batches x 64 ----
    {
        const float gs = *s_gsd;   const float c_gsd  = -0.5f * L2E / (gs * gs);
        const float ns = *s_nrm;   const float c_nrm  = -0.5f * L2E / (ns * ns);
        const float ds = *s_dist;  const float c_dist = -0.5f * L2E / (ds * ds);
        int bb = tid >> 6;
        int v  = tid & 63;
        int bc = b0 + bb; if (bc >= B) bc = B - 1;
        const float* vr = views + ((size_t)bc * NV + v) * 7;
        float v0 = vr[0];
        float x4 = vr[4];
        float x5 = vr[5];
        float x6 = vr[6];
        float m  = (v0 == 1.0f) ? 1.0f : 0.0f;
        float x4sq = x4 * x4;
        float arg = fmaf(x4sq * x4sq, c_gsd,
                    fmaf(x5 * x5,     c_nrm,
                         (x6 * x6) *  c_dist));
        w[bb][v] = m * exp2f(arg);
    }

    // ---- hoisted (i,j) decode for half-stage offsets h=0 (q=tid) and h=1 ----
    const int qt = (tid < HQ) ? tid : 0;            // clamped quad slot
    const float vm = (tid < HQ) ? 1.0f : 0.0f;      // validity mask
    int i0, j0, i1, j1;
    {
        int p0 = 4 * qt;
        int i = (int)((127.0f - sqrtf((float)(16129 - 8 * p0))) * 0.5f);
        while (p0 < ((i * (127 - i)) >> 1)) --i;
        while (p0 >= (((i + 1) * (126 - i)) >> 1)) ++i;
        i0 = i; j0 = p0 - ((i * (127 - i)) >> 1) + i + 1;
    }
    {
        int p0 = 4 * (qt + HQ);
        int i = (int)((127.0f - sqrtf((float)(16129 - 8 * p0))) * 0.5f);
        while (p0 < ((i * (127 - i)) >> 1)) --i;
        while (p0 >= (((i + 1) * (126 - i)) >> 1)) ++i;
        i1 = i; j1 = p0 - ((i * (127 - i)) >> 1) + i + 1;
    }

    float acc = 0.0f;

    #define PROC_QUAD(f0, f1, f2, istart, jstart, wrow)                        \
    {                                                                          \
        int i = (istart), j = (jstart);                                        \
        float pm[4] = { ((f0).x != 0.0f) ? vm : 0.0f,                          \
                        ((f0).w != 0.0f) ? vm : 0.0f,                          \
                        ((f1).z != 0.0f) ? vm : 0.0f,                          \
                        ((f2).y != 0.0f) ? vm : 0.0f };                        \
        float av[4] = { (f0).y, (f1).x, (f1).w, (f2).z };                      \
        float sv[4] = { (f0).z, (f1).y, (f2).x, (f2).w };                      \
        _Pragma("unroll")                                                      \
        for (int k = 0; k < 4; ++k) {                                          \
            float a = av[k];                                                   \
            float s = sv[k];                                                   \
            float m = (a == TH) ? 0.0f : pm[k];                                \
            float ca = (a < TH) ? c_a1 : c_a2;                                 \
            float arg = fmaf(a * a, ca, (s * s) * c_sc);                       \
            float e = exp2f(arg);                                              \
            acc = fmaf(m * e, (wrow)[i] * (wrow)[j], acc);                     \
            ++j;                                                               \
            if (j == NV) { ++i; j = i + 1; }                                   \
        }                                                                      \
    }

    // ---- pipelined mainloop over 8 stages (4 batches x 2 halves) ----
    #pragma unroll
    for (int s = 0; s < NST; ++s) {
        if (s + 1 < NST) {
            ISSUE_STAGE(s + 1);
            asm volatile("cp.async.wait_group 1;");
        } else {
            asm volatile("cp.async.wait_group 0;");
        }
        __syncthreads();                       // stage s data visible to all

        const int bb = s >> 1;
        const float4* buf = ((s & 1) ? sbuf[1] : sbuf[0]);
        float4 f0 = buf[3 * qt + 0];
        float4 f1 = buf[3 * qt + 1];
        float4 f2 = buf[3 * qt + 2];
        if ((s & 1) == 0) {
            PROC_QUAD(f0, f1, f2, i0, j0, w[bb]);
        } else {
            PROC_QUAD(f0, f1, f2, i1, j1, w[bb]);
            // batch bb finished: stash partial sums (distinct slots, no sync)
            float a = acc;
            #pragma unroll
            for (int o = 16; o > 0; o >>= 1)
                a += __shfl_down_sync(0xffffffffu, a, o);
            if ((tid & 31) == 0) warpsum[bb][tid >> 5] = a;
            acc = 0.0f;
        }
        __syncthreads();                       // done reading before reuse
    }
    #undef PROC_QUAD
    #undef ISSUE_STAGE

    // ---- fused epilogue: 32 lanes reduce 4 batches x 8 warp-partials ----
    if (tid < 32) {
        const int bb = tid >> 3;
        const int k  = tid & 7;
        float p = warpsum[bb][k];
        p += __shfl_down_sync(0xffffffffu, p, 4);
        p += __shfl_down_sync(0xffffffffu, p, 2);
        p += __shfl_down_sync(0xffffffffu, p, 1);
        if (k == 0 && (b0 + bb) < B) out[b0 + bb] = p;
    }
}

extern "C" void kernel_launch(void* const* d_in, const int* in_sizes, int n_in,
                              void* d_out, int out_size) {
    const float* views  = (const float*)d_in[0];
    const float* pairs  = (const float*)d_in[1];
    // d_in[2] = point_attribute (unused by reference computation)
    const float* a1     = (const float*)d_in[3];
    const float* a2     = (const float*)d_in[4];
    const float* gsd    = (const float*)d_in[5];
    const float* scale  = (const float*)d_in[6];
    const float* nrm    = (const float*)d_in[7];
    const float* dist   = (const float*)d_in[8];
    float* out = (float*)d_out;

    int B = in_sizes[0] / (NV * 7);
    int nblocks = (B + CHUNK - 1) / CHUNK;
    score_kernel<<<nblocks, TPB>>>(views, pairs, a1, a2, gsd, scale, nrm, dist,
                                   out, B);
}

// round 6
// speedup vs baseline: 1.1068x; 1.1068x over previous
#include <cuda_runtime.h>
#include <cstdint>

#define NV   64
#define NP   2016
#define NQ   504
#define HQ   252            // quads per half-batch stage
#define F4S  756            // float4 per stage (half batch)
#define STAGE_BYTES 12096   // F4S * 16
#define BATCH_BYTES 24192   // NP*3*4
#define TPB  256
#define NBUF 4
#define MAXB 8              // max batches per CTA (ceil(4096/592)=7)

__global__ __launch_bounds__(TPB, 4) void score_kernel(
    const float* __restrict__ views,     // [B, 64, 7]
    const float* __restrict__ pairs,     // [B, 2016, 3]
    const float* __restrict__ s_a1,
    const float* __restrict__ s_a2,
    const float* __restrict__ s_gsd,
    const float* __restrict__ s_scale,
    const float* __restrict__ s_nrm,
    const float* __restrict__ s_dist,
    float* __restrict__ out,             // [B]
    int B)
{
    extern __shared__ float4 ring[];               // NBUF * F4S (48384 B)
    __shared__ float    w[MAXB][NV];
    __shared__ float    warpsum[MAXB][TPB / 32];
    __shared__ uint64_t mbar[NBUF];

    const int tid  = threadIdx.x;
    const int bx   = blockIdx.x;
    const int gsz  = gridDim.x;

    // batches this CTA owns: bx, bx+gsz, ... < B
    int nb = 0;
    for (int bc = bx; bc < B; bc += gsz) ++nb;
    if (nb > MAXB) nb = MAXB;                      // safety (shapes fixed)
    const int nst = 2 * nb;                        // half-batch stages

    const uint32_t ring_s = (uint32_t)__cvta_generic_to_shared(ring);
    const uint32_t mbar_s = (uint32_t)__cvta_generic_to_shared(mbar);
    const char* pair_base = (const char*)pairs;

    // ---- mbarrier init ----
    if (tid == 0) {
        #pragma unroll
        for (int i = 0; i < NBUF; ++i)
            asm volatile("mbarrier.init.shared.b64 [%0], 1;"
                         :: "r"(mbar_s + 8u * i) : "memory");
    }
    __syncthreads();

    // ---- fill one stage: single thread, bulk copy + expect_tx ----
    #define FILL(s)                                                            \
    {                                                                          \
        int t_  = (s) >> 1;                                                    \
        const char* src = pair_base + (size_t)(bx + t_ * gsz) * BATCH_BYTES    \
                          + ((s) & 1) * STAGE_BYTES;                           \
        uint32_t mb  = mbar_s + 8u * ((s) & 3);                                \
        uint32_t dst = ring_s + (uint32_t)STAGE_BYTES * ((s) & 3);             \
        asm volatile("mbarrier.arrive.expect_tx.shared.b64 _, [%0], %1;"       \
                     :: "r"(mb), "r"((uint32_t)STAGE_BYTES) : "memory");       \
        asm volatile("cp.async.bulk.shared::cluster.global"                    \
                     ".mbarrier::complete_tx::bytes [%0], [%1], %2, [%3];"     \
                     :: "r"(dst), "l"(src), "r"((uint32_t)STAGE_BYTES),        \
                        "r"(mb) : "memory");                                   \
    }

    // Kick off up to NBUF initial fills immediately
    if (tid == 0) {
        for (int s = 0; s < NBUF && s < nst; ++s) FILL(s);
    }

    // ---- scalar params ----
    const float L2E = 1.4426950408889634f;
    const float a1 = *s_a1;
    const float a2 = *s_a2;
    const float c_a1 = -0.5f * L2E / (a1 * a1);
    const float c_a2 = -0.5f * L2E / (a2 * a2);
    const float sc = *s_scale;
    const float c_sc = -0.5f * L2E / (sc * sc);
    const float TH = 20.0f / 90.0f;

    // ---- per-view weights for ALL owned batches (overlaps initial fills) ----
    {
        const float gs = *s_gsd;   const float c_gsd  = -0.5f * L2E / (gs * gs);
        const float ns = *s_nrm;   const float c_nrm  = -0.5f * L2E / (ns * ns);
        const float ds = *s_dist;  const float c_dist = -0.5f * L2E / (ds * ds);
        for (int e = tid; e < nb * NV; e += TPB) {
            int t = e >> 6;
            int v = e & 63;
            const float* vr = views + ((size_t)(bx + t * gsz) * NV + v) * 7;
            float v0 = vr[0];
            float x4 = vr[4];
            float x5 = vr[5];
            float x6 = vr[6];
            float m  = (v0 == 1.0f) ? 1.0f : 0.0f;
            float x4sq = x4 * x4;
            float arg = fmaf(x4sq * x4sq, c_gsd,
                        fmaf(x5 * x5,     c_nrm,
                             (x6 * x6) *  c_dist));
            w[t][v] = m * exp2f(arg);
        }
    }

    // ---- (i,j) decode: once per CTA, reused for every batch ----
    const int qt = (tid < HQ) ? tid : 0;
    const float vm = (tid < HQ) ? 1.0f : 0.0f;
    int i0, j0, i1, j1;
    {
        int p0 = 4 * qt;
        int i = (int)((127.0f - sqrtf((float)(16129 - 8 * p0))) * 0.5f);
        while (p0 < ((i * (127 - i)) >> 1)) --i;
        while (p0 >= (((i + 1) * (126 - i)) >> 1)) ++i;
        i0 = i; j0 = p0 - ((i * (127 - i)) >> 1) + i + 1;
    }
    {
        int p0 = 4 * (qt + HQ);
        int i = (int)((127.0f - sqrtf((float)(16129 - 8 * p0))) * 0.5f);
        while (p0 < ((i * (127 - i)) >> 1)) --i;
        while (p0 >= (((i + 1) * (126 - i)) >> 1)) ++i;
        i1 = i; j1 = p0 - ((i * (127 - i)) >> 1) + i + 1;
    }

    __syncthreads();   // w[] visible before first stage compute

    float acc = 0.0f;

    #define PROC_QUAD(f0, f1, f2, istart, jstart, wrow)                        \
    {                                                                          \
        int i = (istart), j = (jstart);                                        \
        float pm[4] = { ((f0).x != 0.0f) ? vm : 0.0f,                          \
                        ((f0).w != 0.0f) ? vm : 0.0f,                          \
                        ((f1).z != 0.0f) ? vm : 0.0f,                          \
                        ((f2).y != 0.0f) ? vm : 0.0f };                        \
        float av[4] = { (f0).y, (f1).x, (f1).w, (f2).z };                      \
        float sv[4] = { (f0).z, (f1).y, (f2).x, (f2).w };                      \
        _Pragma("unroll")                                                      \
        for (int k = 0; k < 4; ++k) {                                          \
            float a = av[k];                                                   \
            float s = sv[k];                                                   \
            float m = (a == TH) ? 0.0f : pm[k];                                \
            float ca = (a < TH) ? c_a1 : c_a2;                                 \
            float arg = fmaf(a * a, ca, (s * s) * c_sc);                       \
            float e = exp2f(arg);                                              \
            acc = fmaf(m * e, (wrow)[i] * (wrow)[j], acc);                     \
            ++j;                                                               \
            if (j == NV) { ++i; j = i + 1; }                                   \
        }                                                                      \
    }

    // ---- mainloop: consume stages; refill buffer the moment it frees ----
    for (int s = 0; s < nst; ++s) {
        // wait full(s) with acquire
        {
            uint32_t mb = mbar_s + 8u * (s & 3);
            uint32_t parity = (s >> 2) & 1;
            uint32_t done;
            asm volatile(
                "{\n\t"
                ".reg .pred p;\n\t"
                "mbarrier.try_wait.parity.acquire.cta.shared::cta.b64 p, [%1], %2;\n\t"
                "selp.b32 %0, 1, 0, p;\n\t"
                "}" : "=r"(done) : "r"(mb), "r"(parity) : "memory");
            if (!done) {
                asm volatile(
                    "{\n\t"
                    ".reg .pred P1;\n\t"
                    "WL_%=:\n\t"
                    "mbarrier.try_wait.parity.acquire.cta.shared::cta.b64 P1, [%0], %1, 0x989680;\n\t"
                    "@P1 bra.uni WD_%=;\n\t"
                    "bra.uni WL_%=;\n\t"
                    "WD_%=:\n\t"
                    "}" :: "r"(mb), "r"(parity) : "memory");
            }
        }

        const int t = s >> 1;
        const float4* buf = ring + (s & 3) * F4S;
        float4 f0 = buf[3 * qt + 0];
        float4 f1 = buf[3 * qt + 1];
        float4 f2 = buf[3 * qt + 2];
        if ((s & 1) == 0) {
            PROC_QUAD(f0, f1, f2, i0, j0, w[t]);
        } else {
            PROC_QUAD(f0, f1, f2, i1, j1, w[t]);
            float a = acc;
            #pragma unroll
            for (int o = 16; o > 0; o >>= 1)
                a += __shfl_down_sync(0xffffffffu, a, o);
            if ((tid & 31) == 0) warpsum[t][tid >> 5] = a;
            acc = 0.0f;
        }
        __syncthreads();                 // everyone done reading buffer s&3
        if (tid == 0 && s + NBUF < nst) FILL(s + NBUF);
    }
    #undef PROC_QUAD
    #undef FILL

    // ---- fused epilogue: warps 0-1 reduce up to 8 batches x 8 partials ----
    if (tid < 64) {
        const int bb = tid >> 3;
        const int k  = tid & 7;
        float p = (bb < nb) ? warpsum[bb][k] : 0.0f;
        p += __shfl_down_sync(0xffffffffu, p, 4);
        p += __shfl_down_sync(0xffffffffu, p, 2);
        p += __shfl_down_sync(0xffffffffu, p, 1);
        if (k == 0 && bb < nb) out[bx + bb * gsz] = p;
    }
}

extern "C" void kernel_launch(void* const* d_in, const int* in_sizes, int n_in,
                              void* d_out, int out_size) {
    const float* views  = (const float*)d_in[0];
    const float* pairs  = (const float*)d_in[1];
    // d_in[2] = point_attribute (unused by reference computation)
    const float* a1     = (const float*)d_in[3];
    const float* a2     = (const float*)d_in[4];
    const float* gsd    = (const float*)d_in[5];
    const float* scale  = (const float*)d_in[6];
    const float* nrm    = (const float*)d_in[7];
    const float* dist   = (const float*)d_in[8];
    float* out = (float*)d_out;

    int B = in_sizes[0] / (NV * 7);
    int grid = 592;                       // 148 SMs x 4 resident CTAs
    if (grid > B) grid = B;

    cudaFuncSetAttribute(score_kernel,
                         cudaFuncAttributeMaxDynamicSharedMemorySize,
                         NBUF * STAGE_BYTES);
    score_kernel<<<grid, TPB, NBUF * STAGE_BYTES>>>(
        views, pairs, a1, a2, gsd, scale, nrm, dist, out, B);
}

// round 7
// speedup vs baseline: 1.1218x; 1.0135x over previous
#include <cuda_runtime.h>
#include <cstdint>

#define NV   64
#define NP   2016
#define NQ   504
#define HQ   252            // quads per half-batch stage
#define F4S  756            // float4 per stage (half batch)
#define STAGE_BYTES 12096   // F4S * 16
#define BATCH_BYTES 24192   // NP*3*4
#define TPB  256
#define NBUF 4
#define MAXB 8              // max batches per CTA (ceil(4096/592)=7)

__global__ __launch_bounds__(TPB, 4) void score_kernel(
    const float* __restrict__ views,     // [B, 64, 7]
    const float* __restrict__ pairs,     // [B, 2016, 3]
    const float* __restrict__ s_a1,
    const float* __restrict__ s_a2,
    const float* __restrict__ s_gsd,
    const float* __restrict__ s_scale,
    const float* __restrict__ s_nrm,
    const float* __restrict__ s_dist,
    float* __restrict__ out,             // [B]
    int B)
{
    extern __shared__ float4 ring[];               // NBUF * F4S (48384 B)
    __shared__ float    w[MAXB][NV];
    __shared__ float    warpsum[MAXB][TPB / 32];
    __shared__ uint64_t mbar[NBUF];

    const int tid  = threadIdx.x;
    const int bx   = blockIdx.x;
    const int gsz  = gridDim.x;

    // batches this CTA owns: bx, bx+gsz, ... < B
    int nb = (B - bx + gsz - 1) / gsz;
    if (nb > MAXB) nb = MAXB;
    const int nst = 2 * nb;                        // half-batch stages

    const uint32_t ring_s = (uint32_t)__cvta_generic_to_shared(ring);
    const uint32_t mbar_s = (uint32_t)__cvta_generic_to_shared(mbar);
    const char* pair_base = (const char*)pairs;

    // ---- mbarrier init ----
    if (tid == 0) {
        #pragma unroll
        for (int i = 0; i < NBUF; ++i)
            asm volatile("mbarrier.init.shared.b64 [%0], 1;"
                         :: "r"(mbar_s + 8u * i) : "memory");
    }
    __syncthreads();

    // ---- fill one stage: single thread, bulk copy + expect_tx ----
    #define FILL(s)                                                            \
    {                                                                          \
        int t_  = (s) >> 1;                                                    \
        const char* src = pair_base + (size_t)(bx + t_ * gsz) * BATCH_BYTES    \
                          + ((s) & 1) * STAGE_BYTES;                           \
        uint32_t mb  = mbar_s + 8u * ((s) & 3);                                \
        uint32_t dst = ring_s + (uint32_t)STAGE_BYTES * ((s) & 3);             \
        asm volatile("mbarrier.arrive.expect_tx.shared.b64 _, [%0], %1;"       \
                     :: "r"(mb), "r"((uint32_t)STAGE_BYTES) : "memory");       \
        asm volatile("cp.async.bulk.shared::cluster.global"                    \
                     ".mbarrier::complete_tx::bytes [%0], [%1], %2, [%3];"     \
                     :: "r"(dst), "l"(src), "r"((uint32_t)STAGE_BYTES),        \
                        "r"(mb) : "memory");                                   \
    }

    // Kick off up to NBUF initial fills immediately
    if (tid == 0) {
        for (int s = 0; s < NBUF && s < nst; ++s) FILL(s);
    }

    // ---- scalar params ----
    const float L2E = 1.4426950408889634f;
    const float a1 = *s_a1;
    const float a2 = *s_a2;
    const float c_a1 = -0.5f * L2E / (a1 * a1);
    const float c_a2 = -0.5f * L2E / (a2 * a2);
    const float sc = *s_scale;
    const float c_sc = -0.5f * L2E / (sc * sc);
    const float TH = 20.0f / 90.0f;

    // ---- per-view weights for ALL owned batches (overlaps initial fills) ----
    {
        const float gs = *s_gsd;   const float c_gsd  = -0.5f * L2E / (gs * gs);
        const float ns = *s_nrm;   const float c_nrm  = -0.5f * L2E / (ns * ns);
        const float ds = *s_dist;  const float c_dist = -0.5f * L2E / (ds * ds);
        for (int e = tid; e < nb * NV; e += TPB) {
            int t = e >> 6;
            int v = e & 63;
            const float* vr = views + ((size_t)(bx + t * gsz) * NV + v) * 7;
            float v0 = vr[0];
            float x4 = vr[4];
            float x5 = vr[5];
            float x6 = vr[6];
            float m  = (v0 == 1.0f) ? 1.0f : 0.0f;
            float x4sq = x4 * x4;
            float arg = fmaf(x4sq * x4sq, c_gsd,
                        fmaf(x5 * x5,     c_nrm,
                             (x6 * x6) *  c_dist));
            w[t][v] = m * exp2f(arg);
        }
    }

    // ---- (i,j) decode: once per CTA, reused for every batch ----
    const int qt = (tid < HQ) ? tid : 0;
    const float vm = (tid < HQ) ? 1.0f : 0.0f;
    int i0, j0, i1, j1;
    {
        int p0 = 4 * qt;
        int i = (int)((127.0f - sqrtf((float)(16129 - 8 * p0))) * 0.5f);
        while (p0 < ((i * (127 - i)) >> 1)) --i;
        while (p0 >= (((i + 1) * (126 - i)) >> 1)) ++i;
        i0 = i; j0 = p0 - ((i * (127 - i)) >> 1) + i + 1;
    }
    {
        int p0 = 4 * (qt + HQ);
        int i = (int)((127.0f - sqrtf((float)(16129 - 8 * p0))) * 0.5f);
        while (p0 < ((i * (127 - i)) >> 1)) --i;
        while (p0 >= (((i + 1) * (126 - i)) >> 1)) ++i;
        i1 = i; j1 = p0 - ((i * (127 - i)) >> 1) + i + 1;
    }

    __syncthreads();   // w[] visible before first stage compute

    float acc = 0.0f;

    #define PROC_QUAD(f0, f1, f2, istart, jstart, wrow)                        \
    {                                                                          \
        int i = (istart), j = (jstart);                                        \
        float pm[4] = { ((f0).x != 0.0f) ? vm : 0.0f,                          \
                        ((f0).w != 0.0f) ? vm : 0.0f,                          \
                        ((f1).z != 0.0f) ? vm : 0.0f,                          \
                        ((f2).y != 0.0f) ? vm : 0.0f };                        \
        float av[4] = { (f0).y, (f1).x, (f1).w, (f2).z };                      \
        float sv[4] = { (f0).z, (f1).y, (f2).x, (f2).w };                      \
        _Pragma("unroll")                                                      \
        for (int k = 0; k < 4; ++k) {                                          \
            float a = av[k];                                                   \
            float s = sv[k];                                                   \
            float m = (a == TH) ? 0.0f : pm[k];                                \
            float ca = (a < TH) ? c_a1 : c_a2;                                 \
            float arg = fmaf(a * a, ca, (s * s) * c_sc);                       \
            float e = exp2f(arg);                                              \
            acc = fmaf(m * e, (wrow)[i] * (wrow)[j], acc);                     \
            ++j;                                                               \
            if (j == NV) { ++i; j = i + 1; }                                   \
        }                                                                      \
    }

    // ---- mainloop: wait -> grab to regs -> sync -> REFILL -> compute ----
    for (int s = 0; s < nst; ++s) {
        // wait full(s) with acquire
        {
            uint32_t mb = mbar_s + 8u * (s & 3);
            uint32_t parity = (s >> 2) & 1;
            uint32_t done;
            asm volatile(
                "{\n\t"
                ".reg .pred p;\n\t"
                "mbarrier.try_wait.parity.acquire.cta.shared::cta.b64 p, [%1], %2;\n\t"
                "selp.b32 %0, 1, 0, p;\n\t"
                "}" : "=r"(done) : "r"(mb), "r"(parity) : "memory");
            if (!done) {
                asm volatile(
                    "{\n\t"
                    ".reg .pred P1;\n\t"
                    "WL_%=:\n\t"
                    "mbarrier.try_wait.parity.acquire.cta.shared::cta.b64 P1, [%0], %1, 0x989680;\n\t"
                    "@P1 bra.uni WD_%=;\n\t"
                    "bra.uni WL_%=;\n\t"
                    "WD_%=:\n\t"
                    "}" :: "r"(mb), "r"(parity) : "memory");
            }
        }

        // Pull stage data into registers
        const int t = s >> 1;
        const float4* buf = ring + (s & 3) * F4S;
        float4 f0 = buf[3 * qt + 0];
        float4 f1 = buf[3 * qt + 1];
        float4 f2 = buf[3 * qt + 2];

        // All threads hold their data in regs -> buffer is free to refill NOW,
        // before we spend time computing.
        __syncthreads();
        if (tid == 0 && s + NBUF < nst) FILL(s + NBUF);

        if ((s & 1) == 0) {
            PROC_QUAD(f0, f1, f2, i0, j0, w[t]);
        } else {
            PROC_QUAD(f0, f1, f2, i1, j1, w[t]);
            // batch t finished: stash partial sums (distinct slots, no sync)
            float a = acc;
            #pragma unroll
            for (int o = 16; o > 0; o >>= 1)
                a += __shfl_down_sync(0xffffffffu, a, o);
            if ((tid & 31) == 0) warpsum[t][tid >> 5] = a;
            acc = 0.0f;
        }
    }
    #undef PROC_QUAD
    #undef FILL

    __syncthreads();   // warpsum visible

    // ---- fused epilogue: warps 0-1 reduce up to 8 batches x 8 partials ----
    if (tid < 64) {
        const int bb = tid >> 3;
        const int k  = tid & 7;
        float p = (bb < nb) ? warpsum[bb][k] : 0.0f;
        p += __shfl_down_sync(0xffffffffu, p, 4);
        p += __shfl_down_sync(0xffffffffu, p, 2);
        p += __shfl_down_sync(0xffffffffu, p, 1);
        if (k == 0 && bb < nb) out[bx + bb * gsz] = p;
    }
}

extern "C" void kernel_launch(void* const* d_in, const int* in_sizes, int n_in,
                              void* d_out, int out_size) {
    const float* views  = (const float*)d_in[0];
    const float* pairs  = (const float*)d_in[1];
    // d_in[2] = point_attribute (unused by reference computation)
    const float* a1     = (const float*)d_in[3];
    const float* a2     = (const float*)d_in[4];
    const float* gsd    = (const float*)d_in[5];
    const float* scale  = (const float*)d_in[6];
    const float* nrm    = (const float*)d_in[7];
    const float* dist   = (const float*)d_in[8];
    float* out = (float*)d_out;

    int B = in_sizes[0] / (NV * 7);
    int grid = 592;                       // 148 SMs x 4 resident CTAs
    if (grid > B) grid = B;

    cudaFuncSetAttribute(score_kernel,
                         cudaFuncAttributeMaxDynamicSharedMemorySize,
                         NBUF * STAGE_BYTES);
    score_kernel<<<grid, TPB, NBUF * STAGE_BYTES>>>(
        views, pairs, a1, a2, gsd, scale, nrm, dist, out, B);
}